// round 5
// baseline (speedup 1.0000x reference)
#include <cuda_runtime.h>
#include <math.h>
#include <stdint.h>

#define D_MODEL 768
#define D_INNER 1536
#define D_STATE 16
#define D_CONV  4
#define DT_RANK 48
#define BATCH   2
#define SEQ     2048
#define NTOK    (BATCH*SEQ)
#define XPROJ   80
#define CHUNK   64

#define BK      16

// ---------------- scratch (static device globals; no allocs) ----------------
static __device__ float g_xz  [2][NTOK][2*D_INNER];
static __device__ float g_xc  [2][NTOK][D_INNER];
static __device__ float g_xdbl[2][NTOK][XPROJ];
static __device__ float g_dt  [2][NTOK][D_INNER];
static __device__ float g_y   [2][NTOK][D_INNER];

__device__ __forceinline__ float siluf(float v)     { return v / (1.f + __expf(-v)); }
__device__ __forceinline__ float softplusf(float v) { return fmaxf(v, 0.f) + log1pf(__expf(-fabsf(v))); }
__device__ __forceinline__ uint32_t f2tf32(float f) {
    uint32_t r; asm("cvt.rna.tf32.f32 %0, %1;" : "=r"(r) : "f"(f)); return r;
}
__device__ __forceinline__ void mma8(float* d, const uint32_t* a, const uint32_t* b) {
    asm volatile(
        "mma.sync.aligned.m16n8k8.row.col.f32.tf32.tf32.f32 "
        "{%0,%1,%2,%3}, {%4,%5,%6,%7}, {%8,%9}, {%0,%1,%2,%3};"
        : "+f"(d[0]), "+f"(d[1]), "+f"(d[2]), "+f"(d[3])
        : "r"(a[0]), "r"(a[1]), "r"(a[2]), "r"(a[3]), "r"(b[0]), "r"(b[1]));
}

// ---------------------------------------------------------------------------
// Tensor-core GEMM with fragment-ordered SMEM:
//   C[M,Nfull] = A[M,K] * B[Nfull,K]^T   (128x128 CTA tile, BK=16)
// SMEM layout (per buffer, 2048 floats each for A and B):
//  A: tiles (rt=row/16, kt=k/8), base=(rt*2+kt)*128;
//     off = base + ((row&7)*4 + (k&3))*4 + ((row>>3)&1) + 2*((k>>2)&1)
//     -> lane l reads its {a0,a1,a2,a3} as one float4 at base + l*16B.
//  B: tiles (nt=n/8, kt=k/8), base=(nt*2+kt)*64;
//     off = base + ((n&7)*4 + (k&3))*2 + ((k>>2)&1)
//     -> lane l reads its {b0,b1} as one float2 at base + l*8B.
// mode 0: store; mode 2: softplus(v + bias[n]).
// ---------------------------------------------------------------------------
__global__ void __launch_bounds__(256) gemm_tc(
    const float* Aa0, const float* Aa1, const float* Ab0, const float* Ab1,
    int lda, int Ksplit,
    const float* Ba0, const float* Ba1, const float* Bb0, const float* Bb1,
    int ldb,
    float* C, long long cDirStride, int ldc,
    int Nfull, int Ktot,
    const float* bias0, const float* bias1, int mode)
{
    __shared__ float As[2][2048];
    __shared__ float Bs[2][2048];

    const int tid    = threadIdx.x;
    const int lane   = tid & 31;
    const int wid    = tid >> 5;
    const int warp_m = wid & 1;          // 0..1 -> 64 rows
    const int warp_n = wid >> 1;         // 0..3 -> 32 cols
    const int g      = lane >> 2;
    const int t      = lane & 3;
    const int dir    = blockIdx.z;
    const int bm     = blockIdx.y * 128;
    const int bn     = blockIdx.x * 128;

    const float* Aseg0 = dir ? Aa1 : Aa0;
    const float* Aseg1 = dir ? Ab1 : Ab0;
    const float* Bseg0 = dir ? Ba1 : Ba0;
    const float* Bseg1 = dir ? Bb1 : Bb0;
    const float* bias  = dir ? bias1 : bias0;
    float* Cd = C + (long long)dir * cDirStride;

    // producer coordinates: 2 float4 per matrix per chunk
    const int ar[2] = { (0 * 256 + tid) >> 2, (1 * 256 + tid) >> 2 };  // row/n
    const int ac    = (tid & 3) * 4;                                   // k within chunk
    const int kt    = ac >> 3;          // k-tile 0/1
    const int kslot = (ac >> 2) & 1;    // k-half within tile

    // precomputed store offsets (element j adds j*4 for A, j*2 for B)
    int offA[2], offB[2];
#pragma unroll
    for (int i = 0; i < 2; i++) {
        int row = ar[i];
        offA[i] = ((row >> 4) * 2 + kt) * 128 + ((row & 7) * 4) * 4 + ((row >> 3) & 1) + 2 * kslot;
        offB[i] = ((row >> 3) * 2 + kt) * 64  + ((row & 7) * 4) * 2 + kslot;
    }

    float acc[4][4][4];
#pragma unroll
    for (int mi = 0; mi < 4; mi++)
#pragma unroll
        for (int ni = 0; ni < 4; ni++)
#pragma unroll
            for (int r = 0; r < 4; r++) acc[mi][ni][r] = 0.f;

    const int nch = Ktot / BK;
    float4 stA[2], stB[2];

    auto stage = [&](int c) {
        const int k0 = c * BK + ac;
        const float* Asrc = Aseg0; int ka = k0;
        if (k0 >= Ksplit) { Asrc = Aseg1; ka = k0 - Ksplit; }
        const float* Bsrc = Bseg0; int kb = k0;
        if (k0 >= Ksplit) { Bsrc = Bseg1; kb = k0 - Ksplit; }
#pragma unroll
        for (int i = 0; i < 2; i++) {
            stA[i] = *(const float4*)(Asrc + (size_t)(bm + ar[i]) * lda + ka);
            int nb = bn + ar[i];
            stB[i] = (nb < Nfull)
                ? *(const float4*)(Bsrc + (size_t)nb * ldb + kb)
                : make_float4(0.f, 0.f, 0.f, 0.f);
        }
    };
    auto commit = [&](int nb) {
        float* A_ = As[nb];
        float* B_ = Bs[nb];
#pragma unroll
        for (int i = 0; i < 2; i++) {
            A_[offA[i] + 0*4] = __uint_as_float(f2tf32(stA[i].x));
            A_[offA[i] + 1*4] = __uint_as_float(f2tf32(stA[i].y));
            A_[offA[i] + 2*4] = __uint_as_float(f2tf32(stA[i].z));
            A_[offA[i] + 3*4] = __uint_as_float(f2tf32(stA[i].w));
            B_[offB[i] + 0*2] = __uint_as_float(f2tf32(stB[i].x));
            B_[offB[i] + 1*2] = __uint_as_float(f2tf32(stB[i].y));
            B_[offB[i] + 2*2] = __uint_as_float(f2tf32(stB[i].z));
            B_[offB[i] + 3*2] = __uint_as_float(f2tf32(stB[i].w));
        }
    };

    stage(0);
    commit(0);
    __syncthreads();

    for (int c = 0; c < nch; c++) {
        const int b = c & 1;
        if (c + 1 < nch) stage(c + 1);

        const float* A_ = As[b];
        const float* B_ = Bs[b];
#pragma unroll
        for (int ks = 0; ks < 2; ks++) {
            float4 af[4];
            float2 bf[4];
#pragma unroll
            for (int mi = 0; mi < 4; mi++) {
                int tile = ((warp_m * 4 + mi) * 2 + ks) * 128;
                af[mi] = *(const float4*)(A_ + tile + lane * 4);
            }
#pragma unroll
            for (int ni = 0; ni < 4; ni++) {
                int tile = ((warp_n * 4 + ni) * 2 + ks) * 64;
                bf[ni] = *(const float2*)(B_ + tile + lane * 2);
            }
#pragma unroll
            for (int mi = 0; mi < 4; mi++) {
                uint32_t au[4] = { __float_as_uint(af[mi].x), __float_as_uint(af[mi].y),
                                   __float_as_uint(af[mi].z), __float_as_uint(af[mi].w) };
#pragma unroll
                for (int ni = 0; ni < 4; ni++) {
                    uint32_t bu[2] = { __float_as_uint(bf[ni].x), __float_as_uint(bf[ni].y) };
                    mma8(acc[mi][ni], au, bu);
                }
            }
        }

        if (c + 1 < nch) commit(b ^ 1);
        __syncthreads();
    }

    // ---- epilogue: registers -> gmem ----
#pragma unroll
    for (int mi = 0; mi < 4; mi++) {
        int row = bm + warp_m * 64 + mi * 16 + g;
#pragma unroll
        for (int ni = 0; ni < 4; ni++) {
            int col = bn + warp_n * 32 + ni * 8 + t * 2;
            if (col < Nfull) {
                float2 v0 = make_float2(acc[mi][ni][0], acc[mi][ni][1]);
                float2 v1 = make_float2(acc[mi][ni][2], acc[mi][ni][3]);
                if (mode == 2) {
                    float b0 = bias[col], b1 = bias[col + 1];
                    v0.x = softplusf(v0.x + b0); v0.y = softplusf(v0.y + b1);
                    v1.x = softplusf(v1.x + b0); v1.y = softplusf(v1.y + b1);
                }
                *(float2*)(Cd + (size_t)row * ldc + col)       = v0;
                *(float2*)(Cd + (size_t)(row + 8) * ldc + col) = v1;
            }
        }
    }
}

// ---------------------------------------------------------------------------
// Depthwise causal conv (D_CONV=4) + bias + SiLU, both directions.
// ---------------------------------------------------------------------------
__global__ void __launch_bounds__(256) conv_silu_kernel(
    const float* __restrict__ w_f, const float* __restrict__ b_f,
    const float* __restrict__ w_r, const float* __restrict__ b_r)
{
    int d = blockIdx.x * 256 + threadIdx.x;
    int t = blockIdx.y;
    int zb = blockIdx.z;
    int dir = zb >> 1, b = zb & 1;

    const float* w  = dir ? w_r : w_f;
    float acc = (dir ? b_r : b_f)[d];
#pragma unroll
    for (int k = 0; k < D_CONV; k++) {
        int tt = dir ? (t + (D_CONV - 1) - k) : (t - (D_CONV - 1) + k);
        if (tt >= 0 && tt < SEQ)
            acc = fmaf(w[d * D_CONV + k], g_xz[dir][b * SEQ + tt][d], acc);
    }
    g_xc[dir][b * SEQ + t][d] = siluf(acc);
}

// ---------------------------------------------------------------------------
// Selective scan. One thread per (dir, b, d) channel, sequential over SEQ.
// ---------------------------------------------------------------------------
__global__ void __launch_bounds__(128) scan_kernel(
    const float* __restrict__ Alog_f, const float* __restrict__ D_f,
    const float* __restrict__ Alog_r, const float* __restrict__ D_r)
{
    int dir = blockIdx.z;
    int b   = blockIdx.y;
    int d   = blockIdx.x * 128 + threadIdx.x;

    const float* Alog = dir ? Alog_r : Alog_f;
    float Av[D_STATE];
#pragma unroll
    for (int n = 0; n < D_STATE; n++) Av[n] = -__expf(Alog[d * D_STATE + n]);
    float Dv = (dir ? D_r : D_f)[d];

    float h[D_STATE];
#pragma unroll
    for (int n = 0; n < D_STATE; n++) h[n] = 0.f;

    __shared__ float sB[CHUNK][D_STATE];
    __shared__ float sC[CHUNK][D_STATE];

    for (int c = 0; c < SEQ / CHUNK; c++) {
        for (int j = threadIdx.x; j < CHUNK * 2 * D_STATE; j += 128) {
            int lt = j >> 5;
            int cc = j & 31;
            int t = dir ? (SEQ - 1 - (c * CHUNK + lt)) : (c * CHUNK + lt);
            float v = g_xdbl[dir][b * SEQ + t][DT_RANK + cc];
            if (cc < D_STATE) sB[lt][cc] = v;
            else              sC[lt][cc - D_STATE] = v;
        }
        __syncthreads();

        for (int lt = 0; lt < CHUNK; lt++) {
            int tt  = dir ? (SEQ - 1 - (c * CHUNK + lt)) : (c * CHUNK + lt);
            int tok = b * SEQ + tt;
            float dt  = g_dt[dir][tok][d];
            float x   = g_xc[dir][tok][d];
            float dtx = dt * x;
            float y = 0.f;
#pragma unroll
            for (int n = 0; n < D_STATE; n++) {
                float dA = __expf(dt * Av[n]);
                h[n] = fmaf(dA, h[n], dtx * sB[lt][n]);
                y    = fmaf(h[n], sC[lt][n], y);
            }
            float z = g_xz[dir][tok][D_INNER + d];
            g_y[dir][tok][d] = (y + x * Dv) * siluf(z);
        }
        __syncthreads();
    }
}

// ---------------------------------------------------------------------------
extern "C" void kernel_launch(void* const* d_in, const int* in_sizes, int n_in,
                              void* d_out, int out_size)
{
    (void)in_sizes; (void)n_in; (void)out_size;

    const float* hidden   = (const float*)d_in[0];
    const float* inW[2]   = {(const float*)d_in[1],  (const float*)d_in[10]};
    const float* convW[2] = {(const float*)d_in[2],  (const float*)d_in[11]};
    const float* convB[2] = {(const float*)d_in[3],  (const float*)d_in[12]};
    const float* xpW[2]   = {(const float*)d_in[4],  (const float*)d_in[13]};
    const float* dtW[2]   = {(const float*)d_in[5],  (const float*)d_in[14]};
    const float* dtB[2]   = {(const float*)d_in[6],  (const float*)d_in[15]};
    const float* Alog[2]  = {(const float*)d_in[7],  (const float*)d_in[16]};
    const float* Dp[2]    = {(const float*)d_in[8],  (const float*)d_in[17]};
    const float* outW[2]  = {(const float*)d_in[9],  (const float*)d_in[18]};
    float* out = (float*)d_out;

    float *xz, *xc, *xdbl, *dt, *y;
    cudaGetSymbolAddress((void**)&xz,   g_xz);
    cudaGetSymbolAddress((void**)&xc,   g_xc);
    cudaGetSymbolAddress((void**)&xdbl, g_xdbl);
    cudaGetSymbolAddress((void**)&dt,   g_dt);
    cudaGetSymbolAddress((void**)&y,    g_y);

    const long long szXZ   = (long long)NTOK * 2 * D_INNER;
    const long long szXC   = (long long)NTOK * D_INNER;
    const long long szXDBL = (long long)NTOK * XPROJ;

    // 1) in_proj: [4096,768] x [3072,768]^T -> [4096,3072], both dirs via z
    gemm_tc<<<dim3((2 * D_INNER) / 128, NTOK / 128, 2), 256>>>(
        hidden, hidden, hidden, hidden, D_MODEL, D_MODEL,
        inW[0], inW[1], inW[0], inW[1], D_MODEL,
        xz, szXZ, 2 * D_INNER,
        2 * D_INNER, D_MODEL, nullptr, nullptr, 0);

    // 2) depthwise conv + silu
    conv_silu_kernel<<<dim3(D_INNER / 256, SEQ, 4), 256>>>(
        convW[0], convB[0], convW[1], convB[1]);

    // 3) x_proj: [4096,1536] x [80,1536]^T -> [4096,80], both dirs via z
    gemm_tc<<<dim3(1, NTOK / 128, 2), 256>>>(
        xc, xc + szXC, xc, xc + szXC, D_INNER, D_INNER,
        xpW[0], xpW[1], xpW[0], xpW[1], D_INNER,
        xdbl, szXDBL, XPROJ,
        XPROJ, D_INNER, nullptr, nullptr, 0);

    // 4) dt_proj + bias + softplus: [4096,48] x [1536,48]^T -> [4096,1536]
    gemm_tc<<<dim3(D_INNER / 128, NTOK / 128, 2), 256>>>(
        xdbl, xdbl + szXDBL, xdbl, xdbl + szXDBL, XPROJ, DT_RANK,
        dtW[0], dtW[1], dtW[0], dtW[1], DT_RANK,
        dt, szXC, D_INNER,
        D_INNER, DT_RANK, dtB[0], dtB[1], 2);

    // 5) selective scan + skip + gate
    scan_kernel<<<dim3(D_INNER / 128, BATCH, 2), 128>>>(
        Alog[0], Dp[0], Alog[1], Dp[1]);

    // 6) out_proj fused over dirs via concat-K: out = [y0|y1] @ [W0|W1]^T
    gemm_tc<<<dim3(D_MODEL / 128, NTOK / 128, 1), 256>>>(
        y, y, y + szXC, y + szXC, D_INNER, D_INNER,
        outW[0], outW[0], outW[1], outW[1], D_INNER,
        out, 0, D_MODEL,
        D_MODEL, 2 * D_INNER, nullptr, nullptr, 0);
}

// round 6
// speedup vs baseline: 1.1848x; 1.1848x over previous
#include <cuda_runtime.h>
#include <math.h>
#include <stdint.h>

#define D_MODEL 768
#define D_INNER 1536
#define D_STATE 16
#define D_CONV  4
#define DT_RANK 48
#define BATCH   2
#define SEQ     2048
#define NTOK    (BATCH*SEQ)
#define XPROJ   80
#define CHUNK   64

#define BK      32
#define NST     3
#define DYN_SMEM (NST * 4096 * 4 * 2)   // 96KB: NST stages x (A:128x32 + B:128x32) fp32

// ---------------- scratch (static device globals; no allocs) ----------------
static __device__ float g_xz  [2][NTOK][2*D_INNER];   // in_proj out (x|z), exact
static __device__ float g_xc  [2][NTOK][D_INNER];     // conv+silu, exact (scan)
static __device__ float g_xcr [2][NTOK][D_INNER];     // conv+silu, tf32-rounded (gemm A)
static __device__ float g_xdbl[2][NTOK][XPROJ];       // x_proj out, exact (scan B/C)
static __device__ float g_dtr [2][NTOK][64];          // dt_r cols rounded + zero pad (gemm A)
static __device__ float g_dt  [2][NTOK][D_INNER];     // softplus(dt), exact
static __device__ float g_y   [2][NTOK][D_INNER];     // scan out, tf32-rounded (gemm A)
static __device__ float g_hidr[NTOK][D_MODEL];        // hidden, rounded
static __device__ float g_inWr [2][2*D_INNER][D_MODEL];
static __device__ float g_xpWr [2][XPROJ][D_INNER];
static __device__ float g_dtWr [2][D_INNER][64];      // padded K 48->64
static __device__ float g_outWr[2][D_MODEL][D_INNER];

__device__ __forceinline__ float siluf(float v)     { return v / (1.f + __expf(-v)); }
__device__ __forceinline__ float softplusf(float v) { return fmaxf(v, 0.f) + log1pf(__expf(-fabsf(v))); }
__device__ __forceinline__ float rtf(float f) {
    uint32_t r; asm("cvt.rna.tf32.f32 %0, %1;" : "=r"(r) : "f"(f));
    return __uint_as_float(r);
}
__device__ __forceinline__ uint32_t smem_u32(const void* p) {
    uint32_t a;
    asm("{ .reg .u64 t; cvta.to.shared.u64 t, %1; cvt.u32.u64 %0, t; }" : "=r"(a) : "l"(p));
    return a;
}
__device__ __forceinline__ void cpasync16(uint32_t dst, const void* src, bool pred) {
    int sz = pred ? 16 : 0;
    asm volatile("cp.async.cg.shared.global [%0], [%1], 16, %2;"
                 :: "r"(dst), "l"(src), "r"(sz) : "memory");
}
#define CP_COMMIT() asm volatile("cp.async.commit_group;" ::: "memory")
#define CP_WAIT1()  asm volatile("cp.async.wait_group 1;" ::: "memory")

__device__ __forceinline__ void mma8(float* d, const uint32_t* a, const uint32_t* b) {
    asm volatile(
        "mma.sync.aligned.m16n8k8.row.col.f32.tf32.tf32.f32 "
        "{%0,%1,%2,%3}, {%4,%5,%6,%7}, {%8,%9}, {%0,%1,%2,%3};"
        : "+f"(d[0]), "+f"(d[1]), "+f"(d[2]), "+f"(d[3])
        : "r"(a[0]), "r"(a[1]), "r"(a[2]), "r"(a[3]), "r"(b[0]), "r"(b[1]));
}

// ---------------------------------------------------------------------------
// tf32 tensor-core GEMM, cp.async 3-stage, BK=32, 128x128 CTA tile.
//   C[M,Nfull] = A[M,K] * B[Nfull,K]^T, operands pre-rounded to tf32 in gmem.
// A/B as two K-segments (k<Ksplit->seg0 else seg1), per dir=blockIdx.z.
// SMEM: rows of 32 floats (128B), float4 slot c4 swizzled by (c4 ^ (row&7)).
// mode 0: store; 2: softplus(v+bias[n]); 3: store + emit g_dtr (x_proj).
// ---------------------------------------------------------------------------
__global__ void __launch_bounds__(256) gemm_tc(
    const float* Aa0, const float* Aa1, const float* Ab0, const float* Ab1,
    int lda, int Ksplit,
    const float* Ba0, const float* Ba1, const float* Bb0, const float* Bb1,
    int ldb,
    float* C, long long cDirStride, int ldc,
    int Nfull, int Ktot,
    const float* bias0, const float* bias1, int mode)
{
    extern __shared__ float dsm[];
    float* sA = dsm;
    float* sB = dsm + NST * 4096;
    const uint32_t aA = smem_u32(sA);
    const uint32_t aB = smem_u32(sB);

    const int tid    = threadIdx.x;
    const int lane   = tid & 31;
    const int wid    = tid >> 5;
    const int warp_m = wid & 1;
    const int warp_n = wid >> 1;
    const int g      = lane >> 2;
    const int t      = lane & 3;
    const int dir    = blockIdx.z;
    const int bm     = blockIdx.y * 128;
    const int bn     = blockIdx.x * 128;
    const int cm     = warp_m * 64 + g;
    const int cn     = warp_n * 32 + g;

    const float* Aseg0 = dir ? Aa1 : Aa0;
    const float* Aseg1 = dir ? Ab1 : Ab0;
    const float* Bseg0 = dir ? Ba1 : Ba0;
    const float* Bseg1 = dir ? Bb1 : Bb0;
    const float* bias  = dir ? bias1 : bias0;
    float* Cd = C + (long long)dir * cDirStride;

    const int nch = Ktot / BK;

    // producer: 4 float4 per matrix per chunk; f = i*256+tid, row=f>>3, c4=f&7
    auto issue = [&](int c) {
        const int st = c % NST;
        const int k0c = c * BK;
#pragma unroll
        for (int i = 0; i < 4; i++) {
            int f = i * 256 + tid;
            int row = f >> 3;
            int c4  = f & 7;
            int kk  = k0c + c4 * 4;
            uint32_t soff = (uint32_t)(st * 4096 + row * 32 + ((c4 ^ (row & 7)) << 2)) * 4;
            // A
            const float* As_ = Aseg0; int ka = kk;
            if (kk >= Ksplit) { As_ = Aseg1; ka = kk - Ksplit; }
            cpasync16(aA + soff, As_ + (size_t)(bm + row) * lda + ka, true);
            // B
            const float* Bs_ = Bseg0; int kb = kk;
            if (kk >= Ksplit) { Bs_ = Bseg1; kb = kk - Ksplit; }
            int nb = bn + row;
            bool ok = nb < Nfull;
            if (!ok) nb = 0;
            cpasync16(aB + soff, Bs_ + (size_t)nb * ldb + kb, ok);
        }
        CP_COMMIT();
    };

    float acc[4][4][4];
#pragma unroll
    for (int mi = 0; mi < 4; mi++)
#pragma unroll
        for (int ni = 0; ni < 4; ni++)
#pragma unroll
            for (int r = 0; r < 4; r++) acc[mi][ni][r] = 0.f;

    // prologue: NST-1 groups
    issue(0);
    issue(1);

    for (int c = 0; c < nch; c++) {
        CP_WAIT1();
        __syncthreads();

        const float* A_ = sA + (c % NST) * 4096;
        const float* B_ = sB + (c % NST) * 4096;
#pragma unroll
        for (int ks = 0; ks < 4; ks++) {
            const int o0 = (((2 * ks)     ^ g) << 2) + t;
            const int o1 = (((2 * ks + 1) ^ g) << 2) + t;
            uint32_t au[4][4], bu[4][2];
#pragma unroll
            for (int mi = 0; mi < 4; mi++) {
                int r = cm + mi * 16;
                au[mi][0] = __float_as_uint(A_[r * 32 + o0]);
                au[mi][1] = __float_as_uint(A_[(r + 8) * 32 + o0]);
                au[mi][2] = __float_as_uint(A_[r * 32 + o1]);
                au[mi][3] = __float_as_uint(A_[(r + 8) * 32 + o1]);
            }
#pragma unroll
            for (int ni = 0; ni < 4; ni++) {
                int n = cn + ni * 8;
                bu[ni][0] = __float_as_uint(B_[n * 32 + o0]);
                bu[ni][1] = __float_as_uint(B_[n * 32 + o1]);
            }
#pragma unroll
            for (int mi = 0; mi < 4; mi++)
#pragma unroll
                for (int ni = 0; ni < 4; ni++)
                    mma8(acc[mi][ni], au[mi], bu[ni]);
        }

        if (c + NST - 1 < nch) issue(c + NST - 1);
        else                   CP_COMMIT();   // empty group keeps wait arithmetic exact
    }

    // ---- epilogue ----
#pragma unroll
    for (int mi = 0; mi < 4; mi++) {
        int row = bm + warp_m * 64 + mi * 16 + g;
#pragma unroll
        for (int ni = 0; ni < 4; ni++) {
            int col = bn + warp_n * 32 + ni * 8 + t * 2;
            float v00 = acc[mi][ni][0], v01 = acc[mi][ni][1];
            float v10 = acc[mi][ni][2], v11 = acc[mi][ni][3];
            if (mode == 3) {
#pragma unroll
                for (int e = 0; e < 2; e++) {
                    int cc = col + e;
                    if (cc < DT_RANK) {
                        g_dtr[dir][row][cc]     = rtf(e ? v01 : v00);
                        g_dtr[dir][row + 8][cc] = rtf(e ? v11 : v10);
                    } else if (cc < 64) {
                        g_dtr[dir][row][cc]     = 0.f;
                        g_dtr[dir][row + 8][cc] = 0.f;
                    }
                }
            }
            if (col < Nfull) {
                if (mode == 2) {
                    float b0 = bias[col], b1 = bias[col + 1];
                    v00 = softplusf(v00 + b0); v01 = softplusf(v01 + b1);
                    v10 = softplusf(v10 + b0); v11 = softplusf(v11 + b1);
                }
                *(float2*)(Cd + (size_t)row * ldc + col)       = make_float2(v00, v01);
                *(float2*)(Cd + (size_t)(row + 8) * ldc + col) = make_float2(v10, v11);
            }
        }
    }
}

// ---------------------------------------------------------------------------
// Rounding pre-passes
// ---------------------------------------------------------------------------
__global__ void round_k(float* __restrict__ dst, const float* __restrict__ src, int n4) {
    int i = blockIdx.x * blockDim.x + threadIdx.x;
    if (i < n4) {
        float4 v = ((const float4*)src)[i];
        v.x = rtf(v.x); v.y = rtf(v.y); v.z = rtf(v.z); v.w = rtf(v.w);
        ((float4*)dst)[i] = v;
    }
}
__global__ void round_dtw(float* __restrict__ dst, const float* __restrict__ src) {
    int i = blockIdx.x * blockDim.x + threadIdx.x;   // over 1536*64
    if (i < D_INNER * 64) {
        int r = i >> 6, c = i & 63;
        dst[i] = (c < DT_RANK) ? rtf(src[r * DT_RANK + c]) : 0.f;
    }
}

// ---------------------------------------------------------------------------
// Depthwise causal conv (D_CONV=4) + bias + SiLU; writes exact + rounded.
// ---------------------------------------------------------------------------
__global__ void __launch_bounds__(256) conv_silu_kernel(
    const float* __restrict__ w_f, const float* __restrict__ b_f,
    const float* __restrict__ w_r, const float* __restrict__ b_r)
{
    int d = blockIdx.x * 256 + threadIdx.x;
    int t = blockIdx.y;
    int zb = blockIdx.z;
    int dir = zb >> 1, b = zb & 1;

    const float* w  = dir ? w_r : w_f;
    float acc = (dir ? b_r : b_f)[d];
#pragma unroll
    for (int k = 0; k < D_CONV; k++) {
        int tt = dir ? (t + (D_CONV - 1) - k) : (t - (D_CONV - 1) + k);
        if (tt >= 0 && tt < SEQ)
            acc = fmaf(w[d * D_CONV + k], g_xz[dir][b * SEQ + tt][d], acc);
    }
    float v = siluf(acc);
    g_xc [dir][b * SEQ + t][d] = v;
    g_xcr[dir][b * SEQ + t][d] = rtf(v);
}

// ---------------------------------------------------------------------------
// Selective scan; writes tf32-rounded y (sole consumer is out_proj GEMM).
// ---------------------------------------------------------------------------
__global__ void __launch_bounds__(128) scan_kernel(
    const float* __restrict__ Alog_f, const float* __restrict__ D_f,
    const float* __restrict__ Alog_r, const float* __restrict__ D_r)
{
    int dir = blockIdx.z;
    int b   = blockIdx.y;
    int d   = blockIdx.x * 128 + threadIdx.x;

    const float* Alog = dir ? Alog_r : Alog_f;
    float Av[D_STATE];
#pragma unroll
    for (int n = 0; n < D_STATE; n++) Av[n] = -__expf(Alog[d * D_STATE + n]);
    float Dv = (dir ? D_r : D_f)[d];

    float h[D_STATE];
#pragma unroll
    for (int n = 0; n < D_STATE; n++) h[n] = 0.f;

    __shared__ float sB[CHUNK][D_STATE];
    __shared__ float sC[CHUNK][D_STATE];

    for (int c = 0; c < SEQ / CHUNK; c++) {
        for (int j = threadIdx.x; j < CHUNK * 2 * D_STATE; j += 128) {
            int lt = j >> 5;
            int cc = j & 31;
            int t = dir ? (SEQ - 1 - (c * CHUNK + lt)) : (c * CHUNK + lt);
            float v = g_xdbl[dir][b * SEQ + t][DT_RANK + cc];
            if (cc < D_STATE) sB[lt][cc] = v;
            else              sC[lt][cc - D_STATE] = v;
        }
        __syncthreads();

        for (int lt = 0; lt < CHUNK; lt++) {
            int tt  = dir ? (SEQ - 1 - (c * CHUNK + lt)) : (c * CHUNK + lt);
            int tok = b * SEQ + tt;
            float dt  = g_dt[dir][tok][d];
            float x   = g_xc[dir][tok][d];
            float dtx = dt * x;
            float y = 0.f;
#pragma unroll
            for (int n = 0; n < D_STATE; n++) {
                float dA = __expf(dt * Av[n]);
                h[n] = fmaf(dA, h[n], dtx * sB[lt][n]);
                y    = fmaf(h[n], sC[lt][n], y);
            }
            float z = g_xz[dir][tok][D_INNER + d];
            g_y[dir][tok][d] = rtf((y + x * Dv) * siluf(z));
        }
        __syncthreads();
    }
}

// ---------------------------------------------------------------------------
extern "C" void kernel_launch(void* const* d_in, const int* in_sizes, int n_in,
                              void* d_out, int out_size)
{
    (void)in_sizes; (void)n_in; (void)out_size;

    const float* hidden   = (const float*)d_in[0];
    const float* inW[2]   = {(const float*)d_in[1],  (const float*)d_in[10]};
    const float* convW[2] = {(const float*)d_in[2],  (const float*)d_in[11]};
    const float* convB[2] = {(const float*)d_in[3],  (const float*)d_in[12]};
    const float* xpW[2]   = {(const float*)d_in[4],  (const float*)d_in[13]};
    const float* dtW[2]   = {(const float*)d_in[5],  (const float*)d_in[14]};
    const float* dtB[2]   = {(const float*)d_in[6],  (const float*)d_in[15]};
    const float* Alog[2]  = {(const float*)d_in[7],  (const float*)d_in[16]};
    const float* Dp[2]    = {(const float*)d_in[8],  (const float*)d_in[17]};
    const float* outW[2]  = {(const float*)d_in[9],  (const float*)d_in[18]};
    float* out = (float*)d_out;

    float *xz, *xcr, *xdbl, *dtr, *dt, *y, *hidr, *inWr, *xpWr, *dtWr, *outWr;
    cudaGetSymbolAddress((void**)&xz,    g_xz);
    cudaGetSymbolAddress((void**)&xcr,   g_xcr);
    cudaGetSymbolAddress((void**)&xdbl,  g_xdbl);
    cudaGetSymbolAddress((void**)&dtr,   g_dtr);
    cudaGetSymbolAddress((void**)&dt,    g_dt);
    cudaGetSymbolAddress((void**)&y,     g_y);
    cudaGetSymbolAddress((void**)&hidr,  g_hidr);
    cudaGetSymbolAddress((void**)&inWr,  g_inWr);
    cudaGetSymbolAddress((void**)&xpWr,  g_xpWr);
    cudaGetSymbolAddress((void**)&dtWr,  g_dtWr);
    cudaGetSymbolAddress((void**)&outWr, g_outWr);

    cudaFuncSetAttribute(gemm_tc, cudaFuncAttributeMaxDynamicSharedMemorySize, DYN_SMEM);

    const long long szXZ   = (long long)NTOK * 2 * D_INNER;
    const long long szXC   = (long long)NTOK * D_INNER;
    const long long szXDBL = (long long)NTOK * XPROJ;
    const long long szINW  = (long long)2 * D_INNER * D_MODEL;
    const long long szXPW  = (long long)XPROJ * D_INNER;
    const long long szDTW  = (long long)D_INNER * 64;
    const long long szOUTW = (long long)D_MODEL * D_INNER;
    const long long szDTR  = (long long)NTOK * 64;

    // 0) tf32 rounding pre-passes
    auto rl = [](float* d_, const float* s_, long long n) {
        int n4 = (int)(n / 4);
        round_k<<<(n4 + 255) / 256, 256>>>(d_, s_, n4);
    };
    rl(hidr, hidden, (long long)NTOK * D_MODEL);
    rl(inWr,          inW[0],  szINW);
    rl(inWr + szINW,  inW[1],  szINW);
    rl(xpWr,          xpW[0],  szXPW);
    rl(xpWr + szXPW,  xpW[1],  szXPW);
    rl(outWr,         outW[0], szOUTW);
    rl(outWr + szOUTW, outW[1], szOUTW);
    round_dtw<<<(D_INNER * 64 + 255) / 256, 256>>>(dtWr, dtW[0]);
    round_dtw<<<(D_INNER * 64 + 255) / 256, 256>>>(dtWr + szDTW, dtW[1]);

    // 1) in_proj: [4096,768] x [3072,768]^T -> [4096,3072]
    gemm_tc<<<dim3((2 * D_INNER) / 128, NTOK / 128, 2), 256, DYN_SMEM>>>(
        hidr, hidr, hidr, hidr, D_MODEL, D_MODEL,
        inWr, inWr + szINW, inWr, inWr + szINW, D_MODEL,
        xz, szXZ, 2 * D_INNER,
        2 * D_INNER, D_MODEL, nullptr, nullptr, 0);

    // 2) depthwise conv + silu (dual write)
    conv_silu_kernel<<<dim3(D_INNER / 256, SEQ, 4), 256>>>(
        convW[0], convB[0], convW[1], convB[1]);

    // 3) x_proj: [4096,1536] x [80,1536]^T -> [4096,80] + g_dtr side output
    gemm_tc<<<dim3(1, NTOK / 128, 2), 256, DYN_SMEM>>>(
        xcr, xcr + szXC, xcr, xcr + szXC, D_INNER, D_INNER,
        xpWr, xpWr + szXPW, xpWr, xpWr + szXPW, D_INNER,
        xdbl, szXDBL, XPROJ,
        XPROJ, D_INNER, nullptr, nullptr, 3);

    // 4) dt_proj (K padded to 64) + bias + softplus
    gemm_tc<<<dim3(D_INNER / 128, NTOK / 128, 2), 256, DYN_SMEM>>>(
        dtr, dtr + szDTR, dtr, dtr + szDTR, 64, 64,
        dtWr, dtWr + szDTW, dtWr, dtWr + szDTW, 64,
        dt, szXC, D_INNER,
        D_INNER, 64, dtB[0], dtB[1], 2);

    // 5) selective scan + skip + gate (writes rounded y)
    scan_kernel<<<dim3(D_INNER / 128, BATCH, 2), 128>>>(
        Alog[0], Dp[0], Alog[1], Dp[1]);

    // 6) out_proj fused over dirs via concat-K: out = [y0|y1] @ [W0|W1]^T
    gemm_tc<<<dim3(D_MODEL / 128, NTOK / 128, 1), 256, DYN_SMEM>>>(
        y, y, y + szXC, y + szXC, D_INNER, D_INNER,
        outWr, outWr, outWr + szOUTW, outWr + szOUTW, D_INNER,
        out, 0, D_MODEL,
        D_MODEL, 2 * D_INNER, nullptr, nullptr, 0);
}

// round 7
// speedup vs baseline: 1.2830x; 1.0829x over previous
#include <cuda_runtime.h>
#include <math.h>
#include <stdint.h>

#define D_MODEL 768
#define D_INNER 1536
#define D_STATE 16
#define D_CONV  4
#define DT_RANK 48
#define BATCH   2
#define SEQ     2048
#define NTOK    (BATCH*SEQ)
#define XPROJ   80
#define CHUNK   64

#define BK      32
#define NST     3
#define STAGE_B 16384                    // bytes per stage per matrix (128x32 f32)
#define DYN_SMEM (NST * STAGE_B * 2)     // 96KB

// ---------------- scratch (static device globals; no allocs) ----------------
static __device__ float g_xz    [2][NTOK][2*D_INNER];
static __device__ float g_xc    [2][NTOK][D_INNER];      // conv+silu exact (scan)
static __device__ float g_xcr   [2][NTOK][D_INNER];      // conv+silu rounded (gemm A)
static __device__ float g_xdbl  [2][NTOK][XPROJ];        // x_proj exact (scan B/C)
static __device__ float g_xppart[8][NTOK][XPROJ];        // x_proj split-K partials
static __device__ float g_dtr   [2][NTOK][64];           // dt_r rounded + zero pad
static __device__ float g_dt    [2][NTOK][D_INNER];      // softplus(dt)
static __device__ float g_y     [2][NTOK][D_INNER];      // scan out rounded
static __device__ float g_opart [2][NTOK][D_MODEL];      // out_proj per-dir partials
static __device__ float g_hidr  [NTOK][D_MODEL];
static __device__ float g_inWr  [2][2*D_INNER][D_MODEL];
static __device__ float g_xpWr  [2][XPROJ][D_INNER];
static __device__ float g_dtWr  [2][D_INNER][64];
static __device__ float g_outWr [2][D_MODEL][D_INNER];

__device__ __forceinline__ float siluf(float v)     { return v / (1.f + __expf(-v)); }
__device__ __forceinline__ float softplusf(float v) { return fmaxf(v, 0.f) + log1pf(__expf(-fabsf(v))); }
__device__ __forceinline__ float rtf(float f) {
    uint32_t r; asm("cvt.rna.tf32.f32 %0, %1;" : "=r"(r) : "f"(f));
    return __uint_as_float(r);
}
__device__ __forceinline__ uint32_t smem_u32(const void* p) {
    uint32_t a;
    asm("{ .reg .u64 t; cvta.to.shared.u64 t, %1; cvt.u32.u64 %0, t; }" : "=r"(a) : "l"(p));
    return a;
}
__device__ __forceinline__ void cpasync16(uint32_t dst, const void* src, bool pred) {
    int sz = pred ? 16 : 0;                     // src-size 0 -> zero-fill 16B
    asm volatile("cp.async.cg.shared.global [%0], [%1], 16, %2;"
                 :: "r"(dst), "l"(src), "r"(sz) : "memory");
}
#define CP_COMMIT() asm volatile("cp.async.commit_group;" ::: "memory")
#define CP_WAIT1()  asm volatile("cp.async.wait_group 1;" ::: "memory")

__device__ __forceinline__ void mma8(float* d, const uint32_t* a, const uint32_t* b) {
    asm volatile(
        "mma.sync.aligned.m16n8k8.row.col.f32.tf32.tf32.f32 "
        "{%0,%1,%2,%3}, {%4,%5,%6,%7}, {%8,%9}, {%0,%1,%2,%3};"
        : "+f"(d[0]), "+f"(d[1]), "+f"(d[2]), "+f"(d[3])
        : "r"(a[0]), "r"(a[1]), "r"(a[2]), "r"(a[3]), "r"(b[0]), "r"(b[1]));
}

// ---------------------------------------------------------------------------
// tf32 tensor-core GEMM, cp.async 3-stage, BK=32, 128x128 CTA tile.
//   Cz[M,Nfull] = A_dir[M, kBase:kBase+Kloc] * B_dir[N, kBase:kBase+Kloc]^T
// z = blockIdx.z: dir = z / zDiv, split = z % zDiv, kBase = split*Kloc.
// Operands pre-rounded to tf32. mode 0: store; 2: softplus(v + bias[n]).
// ---------------------------------------------------------------------------
__global__ void __launch_bounds__(256) gemm_tc(
    const float* A0, const float* A1, int lda,
    const float* B0, const float* B1, int ldb,
    float* C, long long cZStride, int ldc,
    int Nfull, int Kloc, int zDiv,
    const float* bias0, const float* bias1, int mode)
{
    extern __shared__ float dsm[];
    const uint32_t aA = smem_u32(dsm);
    const uint32_t aB = aA + NST * STAGE_B;

    const int tid    = threadIdx.x;
    const int lane   = tid & 31;
    const int wid    = tid >> 5;
    const int warp_m = wid & 1;
    const int warp_n = wid >> 1;
    const int g      = lane >> 2;
    const int t      = lane & 3;
    const int z      = blockIdx.z;
    const int dir    = z / zDiv;
    const int split  = z - dir * zDiv;
    const int kBase  = split * Kloc;
    const int bm     = blockIdx.y * 128;
    const int bn     = blockIdx.x * 128;
    const int cm     = warp_m * 64 + g;
    const int cn     = warp_n * 32 + g;

    const float* A    = dir ? A1 : A0;
    const float* B    = dir ? B1 : B0;
    const float* bias = dir ? bias1 : bias0;
    float* Cz = C + (long long)z * cZStride;

    // -------- producer state: persistent pointers + fixed smem offsets ------
    const float* pa[4];
    const float* pb[4];
    uint32_t soff[4];
    bool okB[4];
#pragma unroll
    for (int i = 0; i < 4; i++) {
        int f   = i * 256 + tid;
        int row = f >> 3;
        int c4  = f & 7;
        soff[i] = (uint32_t)(row * 32 + ((c4 ^ (row & 7)) << 2)) * 4;
        pa[i] = A + (size_t)(bm + row) * lda + kBase + c4 * 4;
        int nb = bn + row;
        okB[i] = nb < Nfull;
        pb[i] = B + (size_t)(okB[i] ? nb : 0) * ldb + kBase + c4 * 4;
    }
    uint32_t stWr = 0;
    auto issue = [&]() {
#pragma unroll
        for (int i = 0; i < 4; i++) {
            cpasync16(aA + stWr + soff[i], pa[i], true);
            cpasync16(aB + stWr + soff[i], pb[i], okB[i]);
            pa[i] += BK;
            pb[i] += BK;
        }
        CP_COMMIT();
        stWr += STAGE_B;
        if (stWr == NST * STAGE_B) stWr = 0;
    };

    float acc[4][4][4];
#pragma unroll
    for (int mi = 0; mi < 4; mi++)
#pragma unroll
        for (int ni = 0; ni < 4; ni++)
#pragma unroll
            for (int r = 0; r < 4; r++) acc[mi][ni][r] = 0.f;

    const int nch = Kloc / BK;
    issue();
    issue();

    uint32_t stRd = 0;
    for (int c = 0; c < nch; c++) {
        CP_WAIT1();
        __syncthreads();
        if (c + NST - 1 < nch) issue();
        else                   CP_COMMIT();

        const float* A_ = dsm + (stRd >> 2);
        const float* B_ = A_ + NST * 4096;
        stRd += STAGE_B;
        if (stRd == NST * STAGE_B) stRd = 0;

#pragma unroll
        for (int ks = 0; ks < 4; ks++) {
            const int o0 = (((2 * ks)     ^ g) << 2) + t;
            const int o1 = (((2 * ks + 1) ^ g) << 2) + t;
            uint32_t au[4][4], bu[4][2];
#pragma unroll
            for (int mi = 0; mi < 4; mi++) {
                int r = cm + mi * 16;
                au[mi][0] = __float_as_uint(A_[r * 32 + o0]);
                au[mi][1] = __float_as_uint(A_[(r + 8) * 32 + o0]);
                au[mi][2] = __float_as_uint(A_[r * 32 + o1]);
                au[mi][3] = __float_as_uint(A_[(r + 8) * 32 + o1]);
            }
#pragma unroll
            for (int ni = 0; ni < 4; ni++) {
                int n = cn + ni * 8;
                bu[ni][0] = __float_as_uint(B_[n * 32 + o0]);
                bu[ni][1] = __float_as_uint(B_[n * 32 + o1]);
            }
#pragma unroll
            for (int mi = 0; mi < 4; mi++)
#pragma unroll
                for (int ni = 0; ni < 4; ni++)
                    mma8(acc[mi][ni], au[mi], bu[ni]);
        }
    }

    // ---- epilogue ----
#pragma unroll
    for (int mi = 0; mi < 4; mi++) {
        int row = bm + warp_m * 64 + mi * 16 + g;
#pragma unroll
        for (int ni = 0; ni < 4; ni++) {
            int col = bn + warp_n * 32 + ni * 8 + t * 2;
            if (col < Nfull) {
                float v00 = acc[mi][ni][0], v01 = acc[mi][ni][1];
                float v10 = acc[mi][ni][2], v11 = acc[mi][ni][3];
                if (mode == 2) {
                    float b0 = bias[col], b1 = bias[col + 1];
                    v00 = softplusf(v00 + b0); v01 = softplusf(v01 + b1);
                    v10 = softplusf(v10 + b0); v11 = softplusf(v11 + b1);
                }
                *(float2*)(Cz + (size_t)row * ldc + col)       = make_float2(v00, v01);
                *(float2*)(Cz + (size_t)(row + 8) * ldc + col) = make_float2(v10, v11);
            }
        }
    }
}

// ---------------------------------------------------------------------------
// Rounding pre-passes (exactly 5 launches so ncu -s 5 lands on in_proj gemm)
// ---------------------------------------------------------------------------
__global__ void round_k(float* __restrict__ dst, const float* __restrict__ src, int n4) {
    int i = blockIdx.x * blockDim.x + threadIdx.x;
    if (i < n4) {
        float4 v = ((const float4*)src)[i];
        v.x = rtf(v.x); v.y = rtf(v.y); v.z = rtf(v.z); v.w = rtf(v.w);
        ((float4*)dst)[i] = v;
    }
}
__global__ void round2_k(float* __restrict__ d0, const float* __restrict__ s0,
                         float* __restrict__ d1, const float* __restrict__ s1, int n4) {
    int i = blockIdx.x * blockDim.x + threadIdx.x;
    if (i < n4) {
        float4 v = ((const float4*)s0)[i];
        v.x = rtf(v.x); v.y = rtf(v.y); v.z = rtf(v.z); v.w = rtf(v.w);
        ((float4*)d0)[i] = v;
        float4 w = ((const float4*)s1)[i];
        w.x = rtf(w.x); w.y = rtf(w.y); w.z = rtf(w.z); w.w = rtf(w.w);
        ((float4*)d1)[i] = w;
    }
}
__global__ void round_dtw2(float* __restrict__ d0, const float* __restrict__ s0,
                           float* __restrict__ d1, const float* __restrict__ s1) {
    int i = blockIdx.x * blockDim.x + threadIdx.x;   // over 1536*64
    if (i < D_INNER * 64) {
        int r = i >> 6, c = i & 63;
        d0[i] = (c < DT_RANK) ? rtf(s0[r * DT_RANK + c]) : 0.f;
        d1[i] = (c < DT_RANK) ? rtf(s1[r * DT_RANK + c]) : 0.f;
    }
}

// ---------------------------------------------------------------------------
// x_proj split-K reduction: sum 4 partials -> xdbl (exact) + dtr (rounded/pad)
// ---------------------------------------------------------------------------
__global__ void xp_reduce_kernel() {
    int i = blockIdx.x * blockDim.x + threadIdx.x;   // over 2*NTOK*80
    if (i >= 2 * NTOK * XPROJ) return;
    int c   = i % XPROJ;
    int tk  = (i / XPROJ) % NTOK;
    int dir = i / (XPROJ * NTOK);
    float s = g_xppart[dir * 4 + 0][tk][c] + g_xppart[dir * 4 + 1][tk][c]
            + g_xppart[dir * 4 + 2][tk][c] + g_xppart[dir * 4 + 3][tk][c];
    g_xdbl[dir][tk][c] = s;
    if (c < DT_RANK)    g_dtr[dir][tk][c] = rtf(s);
    else if (c < 64)    g_dtr[dir][tk][c] = 0.f;
}

// out = partial0 + partial1
__global__ void out_add_kernel(float* __restrict__ out) {
    int i = blockIdx.x * blockDim.x + threadIdx.x;   // over NTOK*D_MODEL/4
    if (i < NTOK * D_MODEL / 4) {
        float4 a = ((const float4*)&g_opart[0][0][0])[i];
        float4 b = ((const float4*)&g_opart[1][0][0])[i];
        a.x += b.x; a.y += b.y; a.z += b.z; a.w += b.w;
        ((float4*)out)[i] = a;
    }
}

// ---------------------------------------------------------------------------
// Depthwise causal conv (D_CONV=4) + bias + SiLU; exact + rounded outputs.
// ---------------------------------------------------------------------------
__global__ void __launch_bounds__(256) conv_silu_kernel(
    const float* __restrict__ w_f, const float* __restrict__ b_f,
    const float* __restrict__ w_r, const float* __restrict__ b_r)
{
    int d = blockIdx.x * 256 + threadIdx.x;
    int t = blockIdx.y;
    int zb = blockIdx.z;
    int dir = zb >> 1, b = zb & 1;

    const float* w  = dir ? w_r : w_f;
    float acc = (dir ? b_r : b_f)[d];
#pragma unroll
    for (int k = 0; k < D_CONV; k++) {
        int tt = dir ? (t + (D_CONV - 1) - k) : (t - (D_CONV - 1) + k);
        if (tt >= 0 && tt < SEQ)
            acc = fmaf(w[d * D_CONV + k], g_xz[dir][b * SEQ + tt][d], acc);
    }
    float v = siluf(acc);
    g_xc [dir][b * SEQ + t][d] = v;
    g_xcr[dir][b * SEQ + t][d] = rtf(v);
}

// ---------------------------------------------------------------------------
// Selective scan; writes tf32-rounded y.
// ---------------------------------------------------------------------------
__global__ void __launch_bounds__(128) scan_kernel(
    const float* __restrict__ Alog_f, const float* __restrict__ D_f,
    const float* __restrict__ Alog_r, const float* __restrict__ D_r)
{
    int dir = blockIdx.z;
    int b   = blockIdx.y;
    int d   = blockIdx.x * 128 + threadIdx.x;

    const float* Alog = dir ? Alog_r : Alog_f;
    float Av[D_STATE];
#pragma unroll
    for (int n = 0; n < D_STATE; n++) Av[n] = -__expf(Alog[d * D_STATE + n]);
    float Dv = (dir ? D_r : D_f)[d];

    float h[D_STATE];
#pragma unroll
    for (int n = 0; n < D_STATE; n++) h[n] = 0.f;

    __shared__ float sB[CHUNK][D_STATE];
    __shared__ float sC[CHUNK][D_STATE];

    for (int c = 0; c < SEQ / CHUNK; c++) {
        for (int j = threadIdx.x; j < CHUNK * 2 * D_STATE; j += 128) {
            int lt = j >> 5;
            int cc = j & 31;
            int t = dir ? (SEQ - 1 - (c * CHUNK + lt)) : (c * CHUNK + lt);
            float v = g_xdbl[dir][b * SEQ + t][DT_RANK + cc];
            if (cc < D_STATE) sB[lt][cc] = v;
            else              sC[lt][cc - D_STATE] = v;
        }
        __syncthreads();

        for (int lt = 0; lt < CHUNK; lt++) {
            int tt  = dir ? (SEQ - 1 - (c * CHUNK + lt)) : (c * CHUNK + lt);
            int tok = b * SEQ + tt;
            float dt  = g_dt[dir][tok][d];
            float x   = g_xc[dir][tok][d];
            float dtx = dt * x;
            float y = 0.f;
#pragma unroll
            for (int n = 0; n < D_STATE; n++) {
                float dA = __expf(dt * Av[n]);
                h[n] = fmaf(dA, h[n], dtx * sB[lt][n]);
                y    = fmaf(h[n], sC[lt][n], y);
            }
            float z = g_xz[dir][tok][D_INNER + d];
            g_y[dir][tok][d] = rtf((y + x * Dv) * siluf(z));
        }
        __syncthreads();
    }
}

// ---------------------------------------------------------------------------
extern "C" void kernel_launch(void* const* d_in, const int* in_sizes, int n_in,
                              void* d_out, int out_size)
{
    (void)in_sizes; (void)n_in; (void)out_size;

    const float* hidden   = (const float*)d_in[0];
    const float* inW[2]   = {(const float*)d_in[1],  (const float*)d_in[10]};
    const float* convW[2] = {(const float*)d_in[2],  (const float*)d_in[11]};
    const float* convB[2] = {(const float*)d_in[3],  (const float*)d_in[12]};
    const float* xpW[2]   = {(const float*)d_in[4],  (const float*)d_in[13]};
    const float* dtW[2]   = {(const float*)d_in[5],  (const float*)d_in[14]};
    const float* dtB[2]   = {(const float*)d_in[6],  (const float*)d_in[15]};
    const float* Alog[2]  = {(const float*)d_in[7],  (const float*)d_in[16]};
    const float* Dp[2]    = {(const float*)d_in[8],  (const float*)d_in[17]};
    const float* outW[2]  = {(const float*)d_in[9],  (const float*)d_in[18]};
    float* out = (float*)d_out;

    float *xcr, *dtr, *dt, *y, *hidr, *inWr, *xpWr, *dtWr, *outWr, *xpp, *opart, *xz;
    cudaGetSymbolAddress((void**)&xz,    g_xz);
    cudaGetSymbolAddress((void**)&xcr,   g_xcr);
    cudaGetSymbolAddress((void**)&dtr,   g_dtr);
    cudaGetSymbolAddress((void**)&dt,    g_dt);
    cudaGetSymbolAddress((void**)&y,     g_y);
    cudaGetSymbolAddress((void**)&hidr,  g_hidr);
    cudaGetSymbolAddress((void**)&inWr,  g_inWr);
    cudaGetSymbolAddress((void**)&xpWr,  g_xpWr);
    cudaGetSymbolAddress((void**)&dtWr,  g_dtWr);
    cudaGetSymbolAddress((void**)&outWr, g_outWr);
    cudaGetSymbolAddress((void**)&xpp,   g_xppart);
    cudaGetSymbolAddress((void**)&opart, g_opart);

    cudaFuncSetAttribute(gemm_tc, cudaFuncAttributeMaxDynamicSharedMemorySize, DYN_SMEM);

    const long long szXZ   = (long long)NTOK * 2 * D_INNER;
    const long long szXC   = (long long)NTOK * D_INNER;
    const long long szINW  = (long long)2 * D_INNER * D_MODEL;
    const long long szXPW  = (long long)XPROJ * D_INNER;
    const long long szDTW  = (long long)D_INNER * 64;
    const long long szOUTW = (long long)D_MODEL * D_INNER;
    const long long szDTR  = (long long)NTOK * 64;
    const long long szXPP  = (long long)NTOK * XPROJ;
    const long long szOP   = (long long)NTOK * D_MODEL;

    // 0) tf32 rounding pre-passes — exactly 5 launches
    {
        int n4 = NTOK * D_MODEL / 4;
        round_k<<<(n4 + 255) / 256, 256>>>(hidr, hidden, n4);
        n4 = (int)(szINW / 4);
        round2_k<<<(n4 + 255) / 256, 256>>>(inWr, inW[0], inWr + szINW, inW[1], n4);
        n4 = (int)(szXPW / 4);
        round2_k<<<(n4 + 255) / 256, 256>>>(xpWr, xpW[0], xpWr + szXPW, xpW[1], n4);
        n4 = (int)(szOUTW / 4);
        round2_k<<<(n4 + 255) / 256, 256>>>(outWr, outW[0], outWr + szOUTW, outW[1], n4);
        round_dtw2<<<(D_INNER * 64 + 255) / 256, 256>>>(dtWr, dtW[0], dtWr + szDTW, dtW[1]);
    }

    // 1) in_proj: [4096,768] x [3072,768]^T -> [4096,3072]
    gemm_tc<<<dim3((2 * D_INNER) / 128, NTOK / 128, 2), 256, DYN_SMEM>>>(
        hidr, hidr, D_MODEL,
        inWr, inWr + szINW, D_MODEL,
        xz, szXZ, 2 * D_INNER,
        2 * D_INNER, D_MODEL, 1, nullptr, nullptr, 0);

    // 2) depthwise conv + silu
    conv_silu_kernel<<<dim3(D_INNER / 256, SEQ, 4), 256>>>(
        convW[0], convB[0], convW[1], convB[1]);

    // 3) x_proj split-K x4: z = dir*4 + split, Kloc=384
    gemm_tc<<<dim3(1, NTOK / 128, 8), 256, DYN_SMEM>>>(
        xcr, xcr + szXC, D_INNER,
        xpWr, xpWr + szXPW, D_INNER,
        xpp, szXPP, XPROJ,
        XPROJ, D_INNER / 4, 4, nullptr, nullptr, 0);
    xp_reduce_kernel<<<(2 * NTOK * XPROJ + 255) / 256, 256>>>();

    // 4) dt_proj (K padded to 64) + bias + softplus
    gemm_tc<<<dim3(D_INNER / 128, NTOK / 128, 2), 256, DYN_SMEM>>>(
        dtr, dtr + szDTR, 64,
        dtWr, dtWr + szDTW, 64,
        dt, szXC, D_INNER,
        D_INNER, 64, 1, dtB[0], dtB[1], 2);

    // 5) selective scan + skip + gate
    scan_kernel<<<dim3(D_INNER / 128, BATCH, 2), 128>>>(
        Alog[0], Dp[0], Alog[1], Dp[1]);

    // 6) out_proj per-dir partials (384 CTAs) + add
    gemm_tc<<<dim3(D_MODEL / 128, NTOK / 128, 2), 256, DYN_SMEM>>>(
        y, y + szXC, D_INNER,
        outWr, outWr + szOUTW, D_INNER,
        opart, szOP, D_MODEL,
        D_MODEL, D_INNER, 1, nullptr, nullptr, 0);
    out_add_kernel<<<(NTOK * D_MODEL / 4 + 255) / 256, 256>>>(out);
}